// round 8
// baseline (speedup 1.0000x reference)
#include <cuda_runtime.h>
#include <cuda_bf16.h>
#include <math.h>
#include <stdint.h>

#define B_SZ  16
#define L_SZ  1024
#define DM    166
#define DI    332
#define DS    16
#define DCV   4
#define DTR   11
#define NLAY  3
#define XZW   (2*DI)        // 664
#define DBCW  (DTR + 2*DS)  // 43
#define ROWS  (B_SZ*L_SZ)   // 16384
#define EPSV  1e-5f
#define SEG   32
#define SLEN  (L_SZ/SEG)    // 32

// -------- scratch (device globals; no allocation allowed) --------
__device__ float g_hidden[ROWS*DM];
__device__ float g_resid [ROWS*DM];
__device__ float g_xz    [ROWS*XZW];
__device__ float g_xc    [ROWS*DI];
__device__ float g_dbc   [ROWS*DBCW];
__device__ float g_segP  [B_SZ*SEG*DI*DS];
__device__ float g_segH  [B_SZ*SEG*DI*DS];
__device__ float g_segS  [B_SZ*SEG*DI*DS];
// split bf16 operand buffers
__device__ __nv_bfloat16 g_hnh[ROWS*DM],  g_hnl[ROWS*DM];
__device__ __nv_bfloat16 g_xch[ROWS*DI],  g_xcl[ROWS*DI];
__device__ __nv_bfloat16 g_yh [ROWS*DI],  g_yl [ROWS*DI];
__device__ __nv_bfloat16 g_w1h[NLAY*XZW*DM],  g_w1l[NLAY*XZW*DM];
__device__ __nv_bfloat16 g_w2h[NLAY*DBCW*DI], g_w2l[NLAY*DBCW*DI];
__device__ __nv_bfloat16 g_w3h[NLAY*DM*DI],   g_w3l[NLAY*DM*DI];

// -------- fast transcendental helpers --------
__device__ __forceinline__ float fex2(float x) {
    float r; asm("ex2.approx.ftz.f32 %0, %1;" : "=f"(r) : "f"(x)); return r;
}
__device__ __forceinline__ float flg2(float x) {
    float r; asm("lg2.approx.ftz.f32 %0, %1;" : "=f"(r) : "f"(x)); return r;
}
__device__ __forceinline__ float frcp(float x) {
    float r; asm("rcp.approx.ftz.f32 %0, %1;" : "=f"(r) : "f"(x)); return r;
}
#define LOG2E 1.44269504f
#define LN2   0.69314718f
__device__ __forceinline__ float fsilu(float s) {
    return s * frcp(1.f + fex2(-LOG2E * s));
}
__device__ __forceinline__ float fsoftplus(float a) {
    return (a > 15.f) ? a : LN2 * flg2(1.f + fex2(a * LOG2E));
}
__device__ __forceinline__ void split2(float v, __nv_bfloat16* hp, __nv_bfloat16* lp) {
    __nv_bfloat16 h = __float2bfloat16(v);
    *hp = h;
    *lp = __float2bfloat16(v - __bfloat162float(h));
}

// -------- weight splitter --------
__global__ void k_split(const float* __restrict__ src, __nv_bfloat16* __restrict__ hi,
                        __nv_bfloat16* __restrict__ lo, int n) {
    int i = blockIdx.x * 256 + threadIdx.x;
    if (i >= n) return;
    split2(src[i], hi + i, lo + i);
}

// ==================== pre-split bf16 HMMA GEMM ====================
#define BM 128
#define BN 64
#define BK 32
#define LDK 40   // padded smem row (bf16): 80B stride -> conflict-free ldmatrix phases

__device__ __forceinline__ void mma_bf16(float* c, const uint32_t* a, uint32_t b0, uint32_t b1) {
    asm volatile(
        "mma.sync.aligned.m16n8k16.row.col.f32.bf16.bf16.f32 "
        "{%0,%1,%2,%3}, {%4,%5,%6,%7}, {%8,%9}, {%0,%1,%2,%3};"
        : "+f"(c[0]), "+f"(c[1]), "+f"(c[2]), "+f"(c[3])
        : "r"(a[0]), "r"(a[1]), "r"(a[2]), "r"(a[3]), "r"(b0), "r"(b1));
}
__device__ __forceinline__ void ldsm_x4(uint32_t* r, uint32_t addr) {
    asm volatile("ldmatrix.sync.aligned.m8n8.x4.shared.b16 {%0,%1,%2,%3}, [%4];"
        : "=r"(r[0]), "=r"(r[1]), "=r"(r[2]), "=r"(r[3]) : "r"(addr));
}

template<int K, bool NEVEN>
__global__ void __launch_bounds__(256) k_hgemm(const __nv_bfloat16* __restrict__ Ahg,
                                               const __nv_bfloat16* __restrict__ Alg,
                                               const __nv_bfloat16* __restrict__ Whg,
                                               const __nv_bfloat16* __restrict__ Wlg,
                                               float* __restrict__ C, int N) {
    __shared__ __nv_bfloat16 Ah[BM][LDK];
    __shared__ __nv_bfloat16 Al[BM][LDK];
    __shared__ __nv_bfloat16 Bh[BN][LDK];
    __shared__ __nv_bfloat16 Bl[BN][LDK];

    constexpr int KT = (K + BK - 1) / BK;
    int tid  = threadIdx.x;
    int wid  = tid >> 5;
    int lane = tid & 31;
    int wm = wid & 3;
    int wn = wid >> 2;
    int grp = lane >> 2;
    int tig = lane & 3;
    int m0 = blockIdx.y * BM;
    int n0 = blockIdx.x * BN;

    int arow = tid >> 4, acp = tid & 15;   // loader: row base, uint32-col
    int lq = lane >> 3, lr = lane & 7;
    int frow = (lq & 1) * 8 + lr;
    int fcol = (lq >> 1) * 8;

    uint32_t sAh = (uint32_t)__cvta_generic_to_shared(&Ah[0][0]);
    uint32_t sAl = (uint32_t)__cvta_generic_to_shared(&Al[0][0]);
    uint32_t sBh = (uint32_t)__cvta_generic_to_shared(&Bh[0][0]);
    uint32_t sBl = (uint32_t)__cvta_generic_to_shared(&Bl[0][0]);

    float acc[2][4][4];
#pragma unroll
    for (int i = 0; i < 2; i++)
#pragma unroll
        for (int j = 0; j < 4; j++)
#pragma unroll
            for (int q = 0; q < 4; q++) acc[i][j][q] = 0.f;

    uint32_t rah[8], ral[8], rbh[4], rbl[4];

    // ---- prologue: load tile 0 ----
#pragma unroll
    for (int i = 0; i < 8; i++) {
        int row = arow + i*16;
        int kg = acp*2;
        bool ok = (kg < K);
        rah[i] = ok ? *(const uint32_t*)(Ahg + (size_t)(m0 + row)*K + kg) : 0u;
        ral[i] = ok ? *(const uint32_t*)(Alg + (size_t)(m0 + row)*K + kg) : 0u;
    }
#pragma unroll
    for (int i = 0; i < 4; i++) {
        int row = arow + i*16;
        int kg = acp*2;
        int n = n0 + row;
        bool ok = (n < N && kg < K);
        rbh[i] = ok ? *(const uint32_t*)(Whg + (size_t)n*K + kg) : 0u;
        rbl[i] = ok ? *(const uint32_t*)(Wlg + (size_t)n*K + kg) : 0u;
    }

#pragma unroll 1
    for (int t = 0; t < KT; t++) {
        // ---- store staged regs to smem ----
#pragma unroll
        for (int i = 0; i < 8; i++) {
            int row = arow + i*16;
            *(uint32_t*)&Ah[row][acp*2] = rah[i];
            *(uint32_t*)&Al[row][acp*2] = ral[i];
        }
#pragma unroll
        for (int i = 0; i < 4; i++) {
            int row = arow + i*16;
            *(uint32_t*)&Bh[row][acp*2] = rbh[i];
            *(uint32_t*)&Bl[row][acp*2] = rbl[i];
        }
        __syncthreads();

        // ---- issue next tile's LDGs (overlap with MMAs) ----
        if (t + 1 < KT) {
            int k0 = (t + 1) * BK;
#pragma unroll
            for (int i = 0; i < 8; i++) {
                int row = arow + i*16;
                int kg = k0 + acp*2;
                bool ok = (kg < K);
                rah[i] = ok ? *(const uint32_t*)(Ahg + (size_t)(m0 + row)*K + kg) : 0u;
                ral[i] = ok ? *(const uint32_t*)(Alg + (size_t)(m0 + row)*K + kg) : 0u;
            }
#pragma unroll
            for (int i = 0; i < 4; i++) {
                int row = arow + i*16;
                int kg = k0 + acp*2;
                int n = n0 + row;
                bool ok = (n < N && kg < K);
                rbh[i] = ok ? *(const uint32_t*)(Whg + (size_t)n*K + kg) : 0u;
                rbl[i] = ok ? *(const uint32_t*)(Wlg + (size_t)n*K + kg) : 0u;
            }
        }

        // ---- compute via ldmatrix ----
#pragma unroll
        for (int ks = 0; ks < BK; ks += 16) {
            uint32_t ah[2][4], al[2][4], bh[2][4], bl[2][4];
#pragma unroll
            for (int i = 0; i < 2; i++) {
                uint32_t ro = (uint32_t)((wm*32 + i*16 + frow)*LDK + ks + fcol)*2;
                ldsm_x4(ah[i], sAh + ro);
                ldsm_x4(al[i], sAl + ro);
            }
#pragma unroll
            for (int jj = 0; jj < 2; jj++) {
                uint32_t ro = (uint32_t)((wn*32 + jj*16 + frow)*LDK + ks + fcol)*2;
                ldsm_x4(bh[jj], sBh + ro);
                ldsm_x4(bl[jj], sBl + ro);
            }
#pragma unroll
            for (int i = 0; i < 2; i++)
#pragma unroll
                for (int j = 0; j < 4; j++) {
                    int jj = j >> 1, sel = j & 1;
                    uint32_t b0h = bh[jj][sel], b1h = bh[jj][sel + 2];
                    uint32_t b0l = bl[jj][sel], b1l = bl[jj][sel + 2];
                    mma_bf16(acc[i][j], ah[i], b0h, b1h);
                    mma_bf16(acc[i][j], ah[i], b0l, b1l);
                    mma_bf16(acc[i][j], al[i], b0h, b1h);
                }
        }
        __syncthreads();
    }

    // ---- epilogue ----
#pragma unroll
    for (int i = 0; i < 2; i++) {
#pragma unroll
        for (int j = 0; j < 4; j++) {
            int mb = m0 + wm*32 + i*16 + grp;
            int nb = n0 + wn*32 + j*8 + tig*2;
            if (NEVEN) {
                if (nb < N) {
                    *(float2*)(C + (size_t)mb*N + nb)     = make_float2(acc[i][j][0], acc[i][j][1]);
                    *(float2*)(C + (size_t)(mb+8)*N + nb) = make_float2(acc[i][j][2], acc[i][j][3]);
                }
            } else {
                if (nb < N)     { C[(size_t)mb*N + nb]       = acc[i][j][0];
                                  C[(size_t)(mb+8)*N + nb]   = acc[i][j][2]; }
                if (nb + 1 < N) { C[(size_t)mb*N + nb+1]     = acc[i][j][1];
                                  C[(size_t)(mb+8)*N + nb+1] = acc[i][j][3]; }
            }
        }
    }
}

// -------- embedding lookup --------
__global__ void k_embed(const int* __restrict__ fasta, const float* __restrict__ emb) {
    int idx = blockIdx.x * blockDim.x + threadIdx.x;
    if (idx >= ROWS*DM) return;
    int r = idx / DM, m = idx - r*DM;
    g_hidden[idx] = emb[fasta[r]*DM + m];
}

// -------- residual add + rmsnorm -> split bf16 --------
__global__ void k_addnorm(const float* __restrict__ nw, int first) {
    int row  = blockIdx.x * 8 + (threadIdx.x >> 5);
    int lane = threadIdx.x & 31;
    const float* hp = g_hidden + row*DM;
    float* rp = g_resid + row*DM;
    float v[6]; float ss = 0.f;
#pragma unroll
    for (int j = 0; j < 6; j++) {
        int i = lane + 32*j;
        float x = 0.f;
        if (i < DM) {
            x = hp[i];
            if (!first) x += rp[i];
            rp[i] = x;
        }
        v[j] = x; ss += x*x;
    }
#pragma unroll
    for (int o = 16; o; o >>= 1) ss += __shfl_xor_sync(0xffffffffu, ss, o);
    float sc = rsqrtf(ss * (1.f/DM) + EPSV);
#pragma unroll
    for (int j = 0; j < 6; j++) {
        int i = lane + 32*j;
        if (i < DM) split2(v[j] * sc * nw[i], g_hnh + row*DM + i, g_hnl + row*DM + i);
    }
}

// -------- final residual add + rmsnorm -> v --------
__global__ void k_finalnorm(const float* __restrict__ nfw, float* __restrict__ vout) {
    int row  = blockIdx.x * 8 + (threadIdx.x >> 5);
    int lane = threadIdx.x & 31;
    const float* hp = g_hidden + row*DM;
    const float* rp = g_resid  + row*DM;
    float v[6]; float ss = 0.f;
#pragma unroll
    for (int j = 0; j < 6; j++) {
        int i = lane + 32*j;
        float x = 0.f;
        if (i < DM) x = hp[i] + rp[i];
        v[j] = x; ss += x*x;
    }
#pragma unroll
    for (int o = 16; o; o >>= 1) ss += __shfl_xor_sync(0xffffffffu, ss, o);
    float sc = rsqrtf(ss * (1.f/DM) + EPSV);
    float* op = vout + row*DM;
#pragma unroll
    for (int j = 0; j < 6; j++) {
        int i = lane + 32*j;
        if (i < DM) op[i] = v[j] * sc * nfw[i];
    }
}

// -------- max over L --------
__global__ void k_maxL(const float* __restrict__ v, float* __restrict__ ve) {
    int w    = blockIdx.x * 8 + (threadIdx.x >> 5);
    int lane = threadIdx.x & 31;
    int b = w / DM, m = w - b*DM;
    float mx = -INFINITY;
    for (int l = lane; l < L_SZ; l += 32)
        mx = fmaxf(mx, v[(b*L_SZ + l)*DM + m]);
#pragma unroll
    for (int o = 16; o; o >>= 1) mx = fmaxf(mx, __shfl_xor_sync(0xffffffffu, mx, o));
    if (lane == 0) ve[b*DM + m] = mx;
}

// -------- causal depthwise conv + SiLU -> fp32 (scan) + split bf16 (GEMM) --------
__global__ void k_conv(const float* __restrict__ cw, const float* __restrict__ cb) {
    int idx = blockIdx.x * blockDim.x + threadIdx.x;
    if (idx >= (ROWS/4)*DI) return;
    int d = idx % DI;
    int q = idx / DI;
    int b = q >> 8;
    int lq = (q & 255) << 2;
    const float* bp = g_xz + (size_t)b*L_SZ*XZW + d;
    float w0 = cw[d*4+0], w1 = cw[d*4+1], w2 = cw[d*4+2], w3 = cw[d*4+3];
    float bb = cb[d];
    float x[7];
    x[0] = (lq >= 3) ? bp[(lq-3)*XZW] : 0.f;
    x[1] = (lq >= 2) ? bp[(lq-2)*XZW] : 0.f;
    x[2] = (lq >= 1) ? bp[(lq-1)*XZW] : 0.f;
    x[3] = bp[(lq+0)*XZW];
    x[4] = bp[(lq+1)*XZW];
    x[5] = bp[(lq+2)*XZW];
    x[6] = bp[(lq+3)*XZW];
    size_t o = ((size_t)b*L_SZ + lq)*DI + d;
#pragma unroll
    for (int j = 0; j < 4; j++) {
        float s = bb;
        s = fmaf(w0, x[j],   s);
        s = fmaf(w1, x[j+1], s);
        s = fmaf(w2, x[j+2], s);
        s = fmaf(w3, x[j+3], s);
        float sv = fsilu(s);
        g_xc[o + j*DI] = sv;
        split2(sv, g_xch + o + j*DI, g_xcl + o + j*DI);
    }
}

// -------- scan pass 1: register-resident, fused dt-projection --------
__global__ void __launch_bounds__(128) k_scan1(const float* __restrict__ A_log,
                                               const float* __restrict__ dtw,
                                               const float* __restrict__ dtb) {
    int d  = blockIdx.x * 128 + threadIdx.x;
    int bs = blockIdx.y;
    int b = bs >> 5, s = bs & 31;
    if (d >= DI) return;

    float A2[DS];
#pragma unroll
    for (int n = 0; n < DS; n++) A2[n] = -__expf(A_log[d*DS + n]) * LOG2E;
    float wv[DTR];
#pragma unroll
    for (int k = 0; k < DTR; k++) wv[k] = dtw[d*DTR + k];
    float bias = dtb[d];

    float h[DS], P[DS];
#pragma unroll
    for (int n = 0; n < DS; n++) { h[n] = 0.f; P[n] = 1.f; }

    int row = b*L_SZ + s*SLEN;
#pragma unroll 2
    for (int l = 0; l < SLEN; l++) {
        const float* dbcp = g_dbc + row*DBCW;
        float acc = bias;
#pragma unroll
        for (int k = 0; k < DTR; k++) acc = fmaf(dbcp[k], wv[k], acc);
        float dt = fsoftplus(acc);
        float xv = g_xc[row*DI + d];
        float dtx = dt * xv;
#pragma unroll
        for (int n = 0; n < DS; n++) {
            float dA = fex2(dt * A2[n]);
            h[n] = fmaf(dA, h[n], dtx * dbcp[DTR + n]);
            P[n] *= dA;
        }
        row++;
    }
    int o = (bs*DI + d) * DS;
#pragma unroll
    for (int n = 0; n < DS; n += 4) {
        *(float4*)(g_segH + o + n) = make_float4(h[n], h[n+1], h[n+2], h[n+3]);
        *(float4*)(g_segP + o + n) = make_float4(P[n], P[n+1], P[n+2], P[n+3]);
    }
}

// -------- scan pass 2: combine segment states --------
__global__ void k_scan2() {
    int idx = blockIdx.x * blockDim.x + threadIdx.x;
    if (idx >= B_SZ*DI*DS) return;
    int dn = idx % (DI*DS);
    int b  = idx / (DI*DS);
    float h = 0.f;
#pragma unroll
    for (int s = 0; s < SEG; s++) {
        int pos = ((b*SEG + s)*DI)*DS + dn;
        g_segS[pos] = h;
        h = fmaf(g_segP[pos], h, g_segH[pos]);
    }
}

// -------- scan pass 3: replay, y -> split bf16 --------
__global__ void __launch_bounds__(128) k_scan3(const float* __restrict__ A_log,
                                               const float* __restrict__ dtw,
                                               const float* __restrict__ dtb,
                                               const float* __restrict__ Dp) {
    int d  = blockIdx.x * 128 + threadIdx.x;
    int bs = blockIdx.y;
    int b = bs >> 5, s = bs & 31;
    if (d >= DI) return;

    float A2[DS];
#pragma unroll
    for (int n = 0; n < DS; n++) A2[n] = -__expf(A_log[d*DS + n]) * LOG2E;
    float wv[DTR];
#pragma unroll
    for (int k = 0; k < DTR; k++) wv[k] = dtw[d*DTR + k];
    float bias = dtb[d];
    float Dv = Dp[d];

    float h[DS];
    {
        int o = (bs*DI + d) * DS;
#pragma unroll
        for (int n = 0; n < DS; n += 4) {
            float4 v = *(const float4*)(g_segS + o + n);
            h[n] = v.x; h[n+1] = v.y; h[n+2] = v.z; h[n+3] = v.w;
        }
    }

    int row = b*L_SZ + s*SLEN;
#pragma unroll 2
    for (int l = 0; l < SLEN; l++) {
        const float* dbcp = g_dbc + row*DBCW;
        float acc = bias;
#pragma unroll
        for (int k = 0; k < DTR; k++) acc = fmaf(dbcp[k], wv[k], acc);
        float dt = fsoftplus(acc);
        float xv = g_xc[row*DI + d];
        float zv = g_xz[row*XZW + DI + d];
        float dtx = dt * xv;
        float yp = 0.f;
#pragma unroll
        for (int n = 0; n < DS; n++) {
            float dA = fex2(dt * A2[n]);
            h[n] = fmaf(dA, h[n], dtx * dbcp[DTR + n]);
            yp = fmaf(h[n], dbcp[DTR + DS + n], yp);
        }
        float yv = fmaf(Dv, xv, yp) * fsilu(zv);
        split2(yv, g_yh + row*DI + d, g_yl + row*DI + d);
        row++;
    }
}

// ----------------------------------------------------------------------------
extern "C" void kernel_launch(void* const* d_in, const int* in_sizes, int n_in,
                              void* d_out, int out_size) {
    const int*   fasta = (const int*)  d_in[0];
    const float* emb   = (const float*)d_in[1];
    const float* in_w  = (const float*)d_in[2];
    const float* cw    = (const float*)d_in[3];
    const float* cb    = (const float*)d_in[4];
    const float* xw    = (const float*)d_in[5];
    const float* dtw   = (const float*)d_in[6];
    const float* dtb   = (const float*)d_in[7];
    const float* Alog  = (const float*)d_in[8];
    const float* Dp    = (const float*)d_in[9];
    const float* ow    = (const float*)d_in[10];
    const float* nw    = (const float*)d_in[11];
    const float* nfw   = (const float*)d_in[12];
    float* out = (float*)d_out;                   // [ve (16*166) | v (16*1024*166)]

    float *xz, *dbc;
    cudaGetSymbolAddress((void**)&xz,  g_xz);
    cudaGetSymbolAddress((void**)&dbc, g_dbc);
    float* hid;
    cudaGetSymbolAddress((void**)&hid, g_hidden);
    __nv_bfloat16 *hnh, *hnl, *xch, *xcl, *yh, *yl;
    __nv_bfloat16 *w1h, *w1l, *w2h, *w2l, *w3h, *w3l;
    cudaGetSymbolAddress((void**)&hnh, g_hnh);  cudaGetSymbolAddress((void**)&hnl, g_hnl);
    cudaGetSymbolAddress((void**)&xch, g_xch);  cudaGetSymbolAddress((void**)&xcl, g_xcl);
    cudaGetSymbolAddress((void**)&yh,  g_yh);   cudaGetSymbolAddress((void**)&yl,  g_yl);
    cudaGetSymbolAddress((void**)&w1h, g_w1h);  cudaGetSymbolAddress((void**)&w1l, g_w1l);
    cudaGetSymbolAddress((void**)&w2h, g_w2h);  cudaGetSymbolAddress((void**)&w2l, g_w2l);
    cudaGetSymbolAddress((void**)&w3h, g_w3h);  cudaGetSymbolAddress((void**)&w3l, g_w3l);

    // ---- pre-split all weights ----
    k_split<<<(NLAY*XZW*DM  + 255)/256, 256>>>(in_w, w1h, w1l, NLAY*XZW*DM);
    k_split<<<(NLAY*DBCW*DI + 255)/256, 256>>>(xw,   w2h, w2l, NLAY*DBCW*DI);
    k_split<<<(NLAY*DM*DI   + 255)/256, 256>>>(ow,   w3h, w3l, NLAY*DM*DI);

    k_embed<<<(ROWS*DM + 255)/256, 256>>>(fasta, emb);

    dim3 sgrid((DI + 127)/128, B_SZ*SEG);

    for (int l = 0; l < NLAY; l++) {
        k_addnorm<<<ROWS/8, 256>>>(nw + l*DM, l == 0);
        // xz = hnorm @ in_w^T   (M=16384, N=664, K=166)
        k_hgemm<DM, true><<<dim3((XZW + BN - 1)/BN, ROWS/BM), 256>>>(
            hnh, hnl, w1h + l*XZW*DM, w1l + l*XZW*DM, xz, XZW);
        // conv + silu
        k_conv<<<((ROWS/4)*DI + 255)/256, 256>>>(cw + l*DI*DCV, cb + l*DI);
        // dbc = xc @ xw^T       (M=16384, N=43, K=332)
        k_hgemm<DI, false><<<dim3(1, ROWS/BM), 256>>>(
            xch, xcl, w2h + l*DBCW*DI, w2l + l*DBCW*DI, dbc, DBCW);
        // chunked selective scan (dt-projection fused)
        k_scan1<<<sgrid, 128>>>(Alog + l*DI*DS, dtw + l*DI*DTR, dtb + l*DI);
        k_scan2<<<(B_SZ*DI*DS + 255)/256, 256>>>();
        k_scan3<<<sgrid, 128>>>(Alog + l*DI*DS, dtw + l*DI*DTR, dtb + l*DI, Dp + l*DI);
        // hidden = y @ ow^T     (M=16384, N=166, K=332)
        k_hgemm<DI, true><<<dim3((DM + BN - 1)/BN, ROWS/BM), 256>>>(
            yh, yl, w3h + l*DM*DI, w3l + l*DM*DI, hid, DM);
    }

    k_finalnorm<<<ROWS/8, 256>>>(nfw, out + B_SZ*DM);
    k_maxL<<<(B_SZ*DM)/8, 256>>>(out + B_SZ*DM, out);
}

// round 9
// speedup vs baseline: 1.1327x; 1.1327x over previous
#include <cuda_runtime.h>
#include <cuda_bf16.h>
#include <math.h>
#include <stdint.h>

#define B_SZ  16
#define L_SZ  1024
#define DM    166
#define DI    332
#define DS    16
#define DCV   4
#define DTR   11
#define NLAY  3
#define XZW   (2*DI)        // 664
#define DBCW  (DTR + 2*DS)  // 43
#define ROWS  (B_SZ*L_SZ)   // 16384
#define EPSV  1e-5f
#define SEG   32
#define SLEN  (L_SZ/SEG)    // 32
#define DMP   (DM/2)        // 83
#define DIP   (DI/2)        // 166

// -------- scratch (device globals; no allocation allowed) --------
__device__ float g_hidden[ROWS*DM];
__device__ float g_resid [ROWS*DM];
__device__ float g_xz    [ROWS*XZW];
__device__ float g_xc    [ROWS*DI];
__device__ float g_dbc   [ROWS*DBCW];
__device__ float g_segP  [B_SZ*SEG*DI*DS];
__device__ float g_segH  [B_SZ*SEG*DI*DS];
__device__ float g_segS  [B_SZ*SEG*DI*DS];
// packed split operands: uint2 = {bf16x2 hi(c0,c1), bf16x2 lo(c0,c1)}
__device__ uint2 g_hnp[ROWS*DMP];
__device__ uint2 g_xcp[ROWS*DIP];
__device__ uint2 g_yp [ROWS*DIP];
__device__ uint2 g_w1p[NLAY*XZW*DMP];
__device__ uint2 g_w2p[NLAY*DBCW*DIP];
__device__ uint2 g_w3p[NLAY*DM*DIP];

// -------- fast transcendental helpers --------
__device__ __forceinline__ float fex2(float x) {
    float r; asm("ex2.approx.ftz.f32 %0, %1;" : "=f"(r) : "f"(x)); return r;
}
__device__ __forceinline__ float flg2(float x) {
    float r; asm("lg2.approx.ftz.f32 %0, %1;" : "=f"(r) : "f"(x)); return r;
}
__device__ __forceinline__ float frcp(float x) {
    float r; asm("rcp.approx.ftz.f32 %0, %1;" : "=f"(r) : "f"(x)); return r;
}
#define LOG2E 1.44269504f
#define LN2   0.69314718f
__device__ __forceinline__ float fsilu(float s) {
    return s * frcp(1.f + fex2(-LOG2E * s));
}
__device__ __forceinline__ float fsoftplus(float a) {
    return (a > 15.f) ? a : LN2 * flg2(1.f + fex2(a * LOG2E));
}
__device__ __forceinline__ uint2 pack_pair(float a, float b) {
    __nv_bfloat16 ha = __float2bfloat16(a);
    __nv_bfloat16 hb = __float2bfloat16(b);
    __nv_bfloat162 hh; hh.x = ha; hh.y = hb;
    __nv_bfloat162 ll;
    ll.x = __float2bfloat16(a - __bfloat162float(ha));
    ll.y = __float2bfloat16(b - __bfloat162float(hb));
    uint2 p;
    p.x = *(uint32_t*)&hh;
    p.y = *(uint32_t*)&ll;
    return p;
}

// -------- weight pair-splitter (flat: rows are K-even so pairs never cross rows) --------
__global__ void k_splitp(const float* __restrict__ src, uint2* __restrict__ dst, int npairs) {
    int i = blockIdx.x * 256 + threadIdx.x;
    if (i >= npairs) return;
    float2 v = ((const float2*)src)[i];
    dst[i] = pack_pair(v.x, v.y);
}

// ==================== packed split-bf16 HMMA GEMM ====================
#define BM 128
#define BN 64
#define BK 32
#define LDK 40   // padded smem row (bf16): 80B stride -> conflict-free ldmatrix phases

__device__ __forceinline__ void mma_bf16(float* c, const uint32_t* a, uint32_t b0, uint32_t b1) {
    asm volatile(
        "mma.sync.aligned.m16n8k16.row.col.f32.bf16.bf16.f32 "
        "{%0,%1,%2,%3}, {%4,%5,%6,%7}, {%8,%9}, {%0,%1,%2,%3};"
        : "+f"(c[0]), "+f"(c[1]), "+f"(c[2]), "+f"(c[3])
        : "r"(a[0]), "r"(a[1]), "r"(a[2]), "r"(a[3]), "r"(b0), "r"(b1));
}
__device__ __forceinline__ void ldsm_x4(uint32_t* r, uint32_t addr) {
    asm volatile("ldmatrix.sync.aligned.m8n8.x4.shared.b16 {%0,%1,%2,%3}, [%4];"
        : "=r"(r[0]), "=r"(r[1]), "=r"(r[2]), "=r"(r[3]) : "r"(addr));
}

template<int K, bool NEVEN>
__global__ void __launch_bounds__(256) k_hgemm(const uint2* __restrict__ Ap,
                                               const uint2* __restrict__ Wp,
                                               float* __restrict__ C, int N) {
    __shared__ __nv_bfloat16 Ah[BM][LDK];
    __shared__ __nv_bfloat16 Al[BM][LDK];
    __shared__ __nv_bfloat16 Bh[BN][LDK];
    __shared__ __nv_bfloat16 Bl[BN][LDK];

    constexpr int KP = K/2;                 // column pairs per row
    constexpr int KT = (K + BK - 1) / BK;
    int tid  = threadIdx.x;
    int wid  = tid >> 5;
    int lane = tid & 31;
    int wm = wid & 3;
    int wn = wid >> 2;
    int grp = lane >> 2;
    int tig = lane & 3;
    int m0 = blockIdx.y * BM;
    int n0 = blockIdx.x * BN;

    int arow = tid >> 4, acp = tid & 15;    // loader: row base, pair-col
    int lq = lane >> 3, lr = lane & 7;
    int frow = (lq & 1) * 8 + lr;
    int fcol = (lq >> 1) * 8;

    uint32_t sAh = (uint32_t)__cvta_generic_to_shared(&Ah[0][0]);
    uint32_t sAl = (uint32_t)__cvta_generic_to_shared(&Al[0][0]);
    uint32_t sBh = (uint32_t)__cvta_generic_to_shared(&Bh[0][0]);
    uint32_t sBl = (uint32_t)__cvta_generic_to_shared(&Bl[0][0]);

    float acc[2][4][4];
#pragma unroll
    for (int i = 0; i < 2; i++)
#pragma unroll
        for (int j = 0; j < 4; j++)
#pragma unroll
            for (int q = 0; q < 4; q++) acc[i][j][q] = 0.f;

    uint2 ra[8], rb[4];
    const uint2 z2 = make_uint2(0u, 0u);

    // ---- prologue: load tile 0 ----
#pragma unroll
    for (int i = 0; i < 8; i++) {
        int row = arow + i*16;
        ra[i] = (acp < KP) ? Ap[(size_t)(m0 + row)*KP + acp] : z2;
    }
#pragma unroll
    for (int i = 0; i < 4; i++) {
        int row = arow + i*16;
        int n = n0 + row;
        rb[i] = (n < N && acp < KP) ? Wp[(size_t)n*KP + acp] : z2;
    }

#pragma unroll 1
    for (int t = 0; t < KT; t++) {
        // ---- store staged regs to smem ----
#pragma unroll
        for (int i = 0; i < 8; i++) {
            int row = arow + i*16;
            *(uint32_t*)&Ah[row][acp*2] = ra[i].x;
            *(uint32_t*)&Al[row][acp*2] = ra[i].y;
        }
#pragma unroll
        for (int i = 0; i < 4; i++) {
            int row = arow + i*16;
            *(uint32_t*)&Bh[row][acp*2] = rb[i].x;
            *(uint32_t*)&Bl[row][acp*2] = rb[i].y;
        }
        __syncthreads();

        // ---- issue next tile's LDGs (overlap with MMAs) ----
        if (t + 1 < KT) {
            int kp = (t + 1) * 16 + acp;
#pragma unroll
            for (int i = 0; i < 8; i++) {
                int row = arow + i*16;
                ra[i] = (kp < KP) ? Ap[(size_t)(m0 + row)*KP + kp] : z2;
            }
#pragma unroll
            for (int i = 0; i < 4; i++) {
                int row = arow + i*16;
                int n = n0 + row;
                rb[i] = (n < N && kp < KP) ? Wp[(size_t)n*KP + kp] : z2;
            }
        }

        // ---- compute via ldmatrix ----
#pragma unroll
        for (int ks = 0; ks < BK; ks += 16) {
            uint32_t ah[2][4], al[2][4], bh[2][4], bl[2][4];
#pragma unroll
            for (int i = 0; i < 2; i++) {
                uint32_t ro = (uint32_t)((wm*32 + i*16 + frow)*LDK + ks + fcol)*2;
                ldsm_x4(ah[i], sAh + ro);
                ldsm_x4(al[i], sAl + ro);
            }
#pragma unroll
            for (int jj = 0; jj < 2; jj++) {
                uint32_t ro = (uint32_t)((wn*32 + jj*16 + frow)*LDK + ks + fcol)*2;
                ldsm_x4(bh[jj], sBh + ro);
                ldsm_x4(bl[jj], sBl + ro);
            }
#pragma unroll
            for (int i = 0; i < 2; i++)
#pragma unroll
                for (int j = 0; j < 4; j++) {
                    int jj = j >> 1, sel = j & 1;
                    uint32_t b0h = bh[jj][sel], b1h = bh[jj][sel + 2];
                    uint32_t b0l = bl[jj][sel], b1l = bl[jj][sel + 2];
                    mma_bf16(acc[i][j], ah[i], b0h, b1h);
                    mma_bf16(acc[i][j], ah[i], b0l, b1l);
                    mma_bf16(acc[i][j], al[i], b0h, b1h);
                }
        }
        __syncthreads();
    }

    // ---- epilogue ----
#pragma unroll
    for (int i = 0; i < 2; i++) {
#pragma unroll
        for (int j = 0; j < 4; j++) {
            int mb = m0 + wm*32 + i*16 + grp;
            int nb = n0 + wn*32 + j*8 + tig*2;
            if (NEVEN) {
                if (nb < N) {
                    *(float2*)(C + (size_t)mb*N + nb)     = make_float2(acc[i][j][0], acc[i][j][1]);
                    *(float2*)(C + (size_t)(mb+8)*N + nb) = make_float2(acc[i][j][2], acc[i][j][3]);
                }
            } else {
                if (nb < N)     { C[(size_t)mb*N + nb]       = acc[i][j][0];
                                  C[(size_t)(mb+8)*N + nb]   = acc[i][j][2]; }
                if (nb + 1 < N) { C[(size_t)mb*N + nb+1]     = acc[i][j][1];
                                  C[(size_t)(mb+8)*N + nb+1] = acc[i][j][3]; }
            }
        }
    }
}

// -------- embedding lookup --------
__global__ void k_embed(const int* __restrict__ fasta, const float* __restrict__ emb) {
    int idx = blockIdx.x * blockDim.x + threadIdx.x;
    if (idx >= ROWS*DM) return;
    int r = idx / DM, m = idx - r*DM;
    g_hidden[idx] = emb[fasta[r]*DM + m];
}

// -------- residual add + rmsnorm -> packed split bf16 --------
__global__ void k_addnorm(const float* __restrict__ nw, int first) {
    int row  = blockIdx.x * 8 + (threadIdx.x >> 5);
    int lane = threadIdx.x & 31;
    const float2* hp = (const float2*)(g_hidden + row*DM);
    float2* rp = (float2*)(g_resid + row*DM);
    const float2* nw2 = (const float2*)nw;
    float2 v[3]; float ss = 0.f;
#pragma unroll
    for (int j = 0; j < 3; j++) {
        int p = lane + 32*j;
        float2 x = make_float2(0.f, 0.f);
        if (p < DMP) {
            x = hp[p];
            if (!first) { float2 r = rp[p]; x.x += r.x; x.y += r.y; }
            rp[p] = x;
        }
        v[j] = x; ss += x.x*x.x + x.y*x.y;
    }
#pragma unroll
    for (int o = 16; o; o >>= 1) ss += __shfl_xor_sync(0xffffffffu, ss, o);
    float sc = rsqrtf(ss * (1.f/DM) + EPSV);
#pragma unroll
    for (int j = 0; j < 3; j++) {
        int p = lane + 32*j;
        if (p < DMP) {
            float2 w = nw2[p];
            g_hnp[row*DMP + p] = pack_pair(v[j].x * sc * w.x, v[j].y * sc * w.y);
        }
    }
}

// -------- final residual add + rmsnorm -> v --------
__global__ void k_finalnorm(const float* __restrict__ nfw, float* __restrict__ vout) {
    int row  = blockIdx.x * 8 + (threadIdx.x >> 5);
    int lane = threadIdx.x & 31;
    const float* hp = g_hidden + row*DM;
    const float* rp = g_resid  + row*DM;
    float v[6]; float ss = 0.f;
#pragma unroll
    for (int j = 0; j < 6; j++) {
        int i = lane + 32*j;
        float x = 0.f;
        if (i < DM) x = hp[i] + rp[i];
        v[j] = x; ss += x*x;
    }
#pragma unroll
    for (int o = 16; o; o >>= 1) ss += __shfl_xor_sync(0xffffffffu, ss, o);
    float sc = rsqrtf(ss * (1.f/DM) + EPSV);
    float* op = vout + row*DM;
#pragma unroll
    for (int j = 0; j < 6; j++) {
        int i = lane + 32*j;
        if (i < DM) op[i] = v[j] * sc * nfw[i];
    }
}

// -------- max over L --------
__global__ void k_maxL(const float* __restrict__ v, float* __restrict__ ve) {
    int w    = blockIdx.x * 8 + (threadIdx.x >> 5);
    int lane = threadIdx.x & 31;
    int b = w / DM, m = w - b*DM;
    float mx = -INFINITY;
    for (int l = lane; l < L_SZ; l += 32)
        mx = fmaxf(mx, v[(b*L_SZ + l)*DM + m]);
#pragma unroll
    for (int o = 16; o; o >>= 1) mx = fmaxf(mx, __shfl_xor_sync(0xffffffffu, mx, o));
    if (lane == 0) ve[b*DM + m] = mx;
}

// -------- causal depthwise conv + SiLU -> fp32 (scan) + packed (GEMM) --------
// thread = (quad of rows, pair of channels)
__global__ void k_conv(const float* __restrict__ cw, const float* __restrict__ cb) {
    int idx = blockIdx.x * blockDim.x + threadIdx.x;
    if (idx >= (ROWS/4)*DIP) return;
    int dp = idx % DIP;
    int q  = idx / DIP;
    int b  = q >> 8;
    int lq = (q & 255) << 2;
    int d  = dp * 2;
    const float* bp = g_xz + (size_t)b*L_SZ*XZW + d;
    float4 wa = *(const float4*)(cw + d*4);
    float4 wb = *(const float4*)(cw + d*4 + 4);
    float2 bb = *(const float2*)(cb + d);
    float2 x[7];
#pragma unroll
    for (int t = 0; t < 3; t++)
        x[t] = (lq >= 3 - t) ? *(const float2*)(bp + (lq - 3 + t)*XZW) : make_float2(0.f, 0.f);
#pragma unroll
    for (int t = 0; t < 4; t++)
        x[3 + t] = *(const float2*)(bp + (lq + t)*XZW);
    size_t o = ((size_t)b*L_SZ + lq)*DI + d;
#pragma unroll
    for (int j = 0; j < 4; j++) {
        float sa = bb.x, sb = bb.y;
        sa = fmaf(wa.x, x[j].x,   sa); sb = fmaf(wb.x, x[j].y,   sb);
        sa = fmaf(wa.y, x[j+1].x, sa); sb = fmaf(wb.y, x[j+1].y, sb);
        sa = fmaf(wa.z, x[j+2].x, sa); sb = fmaf(wb.z, x[j+2].y, sb);
        sa = fmaf(wa.w, x[j+3].x, sa); sb = fmaf(wb.w, x[j+3].y, sb);
        float va = fsilu(sa), vb = fsilu(sb);
        *(float2*)(g_xc + o + j*DI) = make_float2(va, vb);
        g_xcp[((size_t)b*L_SZ + lq + j)*DIP + dp] = pack_pair(va, vb);
    }
}

// -------- scan pass 1: register-resident, fused dt-projection --------
__global__ void __launch_bounds__(128) k_scan1(const float* __restrict__ A_log,
                                               const float* __restrict__ dtw,
                                               const float* __restrict__ dtb) {
    int d  = blockIdx.x * 128 + threadIdx.x;
    int bs = blockIdx.y;
    int b = bs >> 5, s = bs & 31;
    if (d >= DI) return;

    float A2[DS];
#pragma unroll
    for (int n = 0; n < DS; n++) A2[n] = -__expf(A_log[d*DS + n]) * LOG2E;
    float wv[DTR];
#pragma unroll
    for (int k = 0; k < DTR; k++) wv[k] = dtw[d*DTR + k];
    float bias = dtb[d];

    float h[DS], P[DS];
#pragma unroll
    for (int n = 0; n < DS; n++) { h[n] = 0.f; P[n] = 1.f; }

    int row = b*L_SZ + s*SLEN;
#pragma unroll 2
    for (int l = 0; l < SLEN; l++) {
        const float* dbcp = g_dbc + row*DBCW;
        float acc = bias;
#pragma unroll
        for (int k = 0; k < DTR; k++) acc = fmaf(dbcp[k], wv[k], acc);
        float dt = fsoftplus(acc);
        float xv = g_xc[row*DI + d];
        float dtx = dt * xv;
#pragma unroll
        for (int n = 0; n < DS; n++) {
            float dA = fex2(dt * A2[n]);
            h[n] = fmaf(dA, h[n], dtx * dbcp[DTR + n]);
            P[n] *= dA;
        }
        row++;
    }
    int o = (bs*DI + d) * DS;
#pragma unroll
    for (int n = 0; n < DS; n += 4) {
        *(float4*)(g_segH + o + n) = make_float4(h[n], h[n+1], h[n+2], h[n+3]);
        *(float4*)(g_segP + o + n) = make_float4(P[n], P[n+1], P[n+2], P[n+3]);
    }
}

// -------- scan pass 2: combine segment states --------
__global__ void k_scan2() {
    int idx = blockIdx.x * blockDim.x + threadIdx.x;
    if (idx >= B_SZ*DI*DS) return;
    int dn = idx % (DI*DS);
    int b  = idx / (DI*DS);
    float h = 0.f;
#pragma unroll
    for (int s = 0; s < SEG; s++) {
        int pos = ((b*SEG + s)*DI)*DS + dn;
        g_segS[pos] = h;
        h = fmaf(g_segP[pos], h, g_segH[pos]);
    }
}

// -------- scan pass 3: replay, y -> packed split bf16 via lane-pair shfl --------
__global__ void __launch_bounds__(128) k_scan3(const float* __restrict__ A_log,
                                               const float* __restrict__ dtw,
                                               const float* __restrict__ dtb,
                                               const float* __restrict__ Dp) {
    int dg = blockIdx.x * 128 + threadIdx.x;
    int bs = blockIdx.y;
    int b = bs >> 5, s = bs & 31;
    bool valid = (dg < DI);
    // clamp keeps all threads alive (full-mask shfl below); parity preserved
    int d = valid ? dg : (DI - 2 + (threadIdx.x & 1));

    float A2[DS];
#pragma unroll
    for (int n = 0; n < DS; n++) A2[n] = -__expf(A_log[d*DS + n]) * LOG2E;
    float wv[DTR];
#pragma unroll
    for (int k = 0; k < DTR; k++) wv[k] = dtw[d*DTR + k];
    float bias = dtb[d];
    float Dv = Dp[d];

    float h[DS];
    {
        int o = (bs*DI + d) * DS;
#pragma unroll
        for (int n = 0; n < DS; n += 4) {
            float4 v = *(const float4*)(g_segS + o + n);
            h[n] = v.x; h[n+1] = v.y; h[n+2] = v.z; h[n+3] = v.w;
        }
    }

    int row = b*L_SZ + s*SLEN;
#pragma unroll 2
    for (int l = 0; l < SLEN; l++) {
        const float* dbcp = g_dbc + row*DBCW;
        float acc = bias;
#pragma unroll
        for (int k = 0; k < DTR; k++) acc = fmaf(dbcp[k], wv[k], acc);
        float dt = fsoftplus(acc);
        float xv = g_xc[row*DI + d];
        float zv = g_xz[row*XZW + DI + d];
        float dtx = dt * xv;
        float yp = 0.f;
#pragma unroll
        for (int n = 0; n < DS; n++) {
            float dA = fex2(dt * A2[n]);
            h[n] = fmaf(dA, h[n], dtx * dbcp[DTR + n]);
            yp = fmaf(h[n], dbcp[DTR + DS + n], yp);
        }
        float yv = fmaf(Dv, xv, yp) * fsilu(zv);
        float yo = __shfl_down_sync(0xffffffffu, yv, 1);
        if (valid && ((threadIdx.x & 1) == 0))
            g_yp[(size_t)row*DIP + (d >> 1)] = pack_pair(yv, yo);
        row++;
    }
}

// ----------------------------------------------------------------------------
extern "C" void kernel_launch(void* const* d_in, const int* in_sizes, int n_in,
                              void* d_out, int out_size) {
    const int*   fasta = (const int*)  d_in[0];
    const float* emb   = (const float*)d_in[1];
    const float* in_w  = (const float*)d_in[2];
    const float* cw    = (const float*)d_in[3];
    const float* cb    = (const float*)d_in[4];
    const float* xw    = (const float*)d_in[5];
    const float* dtw   = (const float*)d_in[6];
    const float* dtb   = (const float*)d_in[7];
    const float* Alog  = (const float*)d_in[8];
    const float* Dp    = (const float*)d_in[9];
    const float* ow    = (const float*)d_in[10];
    const float* nw    = (const float*)d_in[11];
    const float* nfw   = (const float*)d_in[12];
    float* out = (float*)d_out;                   // [ve (16*166) | v (16*1024*166)]

    float *xz, *dbc, *hid;
    cudaGetSymbolAddress((void**)&xz,  g_xz);
    cudaGetSymbolAddress((void**)&dbc, g_dbc);
    cudaGetSymbolAddress((void**)&hid, g_hidden);
    uint2 *hnp, *xcp, *yp, *w1p, *w2p, *w3p;
    cudaGetSymbolAddress((void**)&hnp, g_hnp);
    cudaGetSymbolAddress((void**)&xcp, g_xcp);
    cudaGetSymbolAddress((void**)&yp,  g_yp);
    cudaGetSymbolAddress((void**)&w1p, g_w1p);
    cudaGetSymbolAddress((void**)&w2p, g_w2p);
    cudaGetSymbolAddress((void**)&w3p, g_w3p);

    // ---- pack all weights (pairs along K; K even for all) ----
    k_splitp<<<(NLAY*XZW*DMP  + 255)/256, 256>>>(in_w, w1p, NLAY*XZW*DMP);
    k_splitp<<<(NLAY*DBCW*DIP + 255)/256, 256>>>(xw,   w2p, NLAY*DBCW*DIP);
    k_splitp<<<(NLAY*DM*DIP   + 255)/256, 256>>>(ow,   w3p, NLAY*DM*DIP);

    k_embed<<<(ROWS*DM + 255)/256, 256>>>(fasta, emb);

    dim3 sgrid((DI + 127)/128, B_SZ*SEG);

    for (int l = 0; l < NLAY; l++) {
        k_addnorm<<<ROWS/8, 256>>>(nw + l*DM, l == 0);
        // xz = hnorm @ in_w^T   (M=16384, N=664, K=166)
        k_hgemm<DM, true><<<dim3((XZW + BN - 1)/BN, ROWS/BM), 256>>>(
            hnp, w1p + (size_t)l*XZW*DMP, xz, XZW);
        // conv + silu
        k_conv<<<((ROWS/4)*DIP + 255)/256, 256>>>(cw + l*DI*DCV, cb + l*DI);
        // dbc = xc @ xw^T       (M=16384, N=43, K=332)
        k_hgemm<DI, false><<<dim3(1, ROWS/BM), 256>>>(
            xcp, w2p + (size_t)l*DBCW*DIP, dbc, DBCW);
        // chunked selective scan (dt-projection fused)
        k_scan1<<<sgrid, 128>>>(Alog + l*DI*DS, dtw + l*DI*DTR, dtb + l*DI);
        k_scan2<<<(B_SZ*DI*DS + 255)/256, 256>>>();
        k_scan3<<<sgrid, 128>>>(Alog + l*DI*DS, dtw + l*DI*DTR, dtb + l*DI, Dp + l*DI);
        // hidden = y @ ow^T     (M=16384, N=166, K=332)
        k_hgemm<DI, true><<<dim3((DM + BN - 1)/BN, ROWS/BM), 256>>>(
            yp, w3p + (size_t)l*DM*DIP, hid, DM);
    }

    k_finalnorm<<<ROWS/8, 256>>>(nfw, out + B_SZ*DM);
    k_maxL<<<(B_SZ*DM)/8, 256>>>(out + B_SZ*DM, out);
}